// round 9
// baseline (speedup 1.0000x reference)
#include <cuda_runtime.h>
#include <cuda_bf16.h>

#define MAX_SEG 16384
#define PAD 8   // one float counter per 32B L2 sector

// Padded scatter accumulators: track/hit in separate arrays, one counter per
// 32B sector. Zero-initialized at module load; corr_kernel self-cleans after
// reading, so every launch starts from a clean state.
__device__ float g_track[MAX_SEG * PAD];
__device__ float g_hit[MAX_SEG * PAD];

// Packed table for the gather phase: ONE 16B read per hit.
//   x = e_track_raw  y = e_track_corr  z = e_hit_raw  w = e_hit_corr
__device__ float4 g_shower[MAX_SEG];

__device__ __forceinline__ void stcs_f4(float4* p, float4 v) {
    asm volatile("st.global.cs.v4.f32 [%0], {%1,%2,%3,%4};"
                 :: "l"(p), "f"(v.x), "f"(v.y), "f"(v.z), "f"(v.w)
                 : "memory");
}

// ---------------------------------------------------------------------------
// Kernel 1: scatter — grid-stride (one balanced wave, no wave quantization).
// Each iteration: 8 hits, loads front-batched, 8 predicated REDs.
// Noise hits (sid == -1) contribute exactly 0 in the reference -> skipped.
// recHitID==1 -> track, ==0 -> hit.
// ---------------------------------------------------------------------------
__global__ void __launch_bounds__(256) scatter8_gs_kernel(
        const int* __restrict__ sid,
        const float* __restrict__ energy,
        const int* __restrict__ rid,
        long ngroups,          // n/8 groups of 8 hits
        long n) {
    long stride = (long)gridDim.x * blockDim.x;
    for (long t = (long)blockIdx.x * blockDim.x + threadIdx.x; t < ngroups;
         t += stride) {
        int4   s0 = __ldg((const int4*)(sid)      + 2*t);
        int4   s1 = __ldg((const int4*)(sid)      + 2*t + 1);
        float4 e0 = __ldg((const float4*)(energy) + 2*t);
        float4 e1 = __ldg((const float4*)(energy) + 2*t + 1);
        int4   r0 = __ldg((const int4*)(rid)      + 2*t);
        int4   r1 = __ldg((const int4*)(rid)      + 2*t + 1);
        int   s[8] = {s0.x, s0.y, s0.z, s0.w, s1.x, s1.y, s1.z, s1.w};
        float e[8] = {e0.x, e0.y, e0.z, e0.w, e1.x, e1.y, e1.z, e1.w};
        int   r[8] = {r0.x, r0.y, r0.z, r0.w, r1.x, r1.y, r1.z, r1.w};
#pragma unroll
        for (int k = 0; k < 8; k++) {
            if (s[k] >= 0) {
                float* p = (r[k] == 1) ? &g_track[(s[k] + 1) * PAD]
                                       : &g_hit[(s[k] + 1) * PAD];
                atomicAdd(p, e[k]);
            }
        }
    }
    // Tail (n % 8 hits): handled by one thread, <= 7 ops.
    if (blockIdx.x == 0 && threadIdx.x == 0) {
        for (long i = ngroups * 8; i < n; i++) {
            int sv = sid[i];
            if (sv >= 0) {
                float* p = (rid[i] == 1) ? &g_track[(sv + 1) * PAD]
                                         : &g_hit[(sv + 1) * PAD];
                atomicAdd(p, energy[i]);
            }
        }
    }
}

// ---------------------------------------------------------------------------
// Kernel 2: per-shower correction + repack into the float4 table + self-clean.
// corr[s] (s>=1) = pcf_ext[alpha_idx[s-1]], pcf_ext[j] = pcf[j] if j < n_hits
// and sid[j] != -1, else 0. corr[0] = 0.
// ---------------------------------------------------------------------------
__global__ void corr_kernel(const int* __restrict__ sid,
                            const float* __restrict__ pcf,
                            const int* __restrict__ a_tracks,
                            const int* __restrict__ a_hits,
                            int n_hits, int nseg) {
    int s = blockIdx.x * blockDim.x + threadIdx.x;
    if (s >= nseg) return;
    float ct = 0.f, ch = 0.f;
    if (s > 0) {
        int jt = a_tracks[s - 1];
        if (jt >= 0 && jt < n_hits && __ldg(sid + jt) != -1) ct = __ldg(pcf + jt);
        int jh = a_hits[s - 1];
        if (jh >= 0 && jh < n_hits && __ldg(sid + jh) != -1) ch = __ldg(pcf + jh);
    }
    float et = g_track[s * PAD];
    float eh = g_hit[s * PAD];
    g_shower[s] = make_float4(et, et * ct, eh, eh * ch);
    g_track[s * PAD] = 0.f;   // clean for the next launch
    g_hit[s * PAD]   = 0.f;
}

// ---------------------------------------------------------------------------
// Kernel 3: gather — grid-stride, 4 hits/iter: 1 int4 sid load ->
// 4 independent random 16B table reads -> 4 coalesced float4 STREAMING stores
// (output never re-read; evict-first preserves L2 for sid/table).
//   [0,n) e_track_raw [n,2n) e_track_corr [2n,3n) e_hit_raw [3n,4n) e_hit_corr
// ---------------------------------------------------------------------------
__global__ void __launch_bounds__(256) gather_gs_kernel(
        const int* __restrict__ sid,
        float* __restrict__ out,
        long nquads, long n) {
    long stride = (long)gridDim.x * blockDim.x;
    for (long t = (long)blockIdx.x * blockDim.x + threadIdx.x; t < nquads;
         t += stride) {
        int4 s4 = __ldg((const int4*)(sid) + t);
        float4 v0 = g_shower[s4.x + 1];
        float4 v1 = g_shower[s4.y + 1];
        float4 v2 = g_shower[s4.z + 1];
        float4 v3 = g_shower[s4.w + 1];
        stcs_f4((float4*)(out)         + t, make_float4(v0.x, v1.x, v2.x, v3.x));
        stcs_f4((float4*)(out + n)     + t, make_float4(v0.y, v1.y, v2.y, v3.y));
        stcs_f4((float4*)(out + 2*n)   + t, make_float4(v0.z, v1.z, v2.z, v3.z));
        stcs_f4((float4*)(out + 3*n)   + t, make_float4(v0.w, v1.w, v2.w, v3.w));
    }
    // Tail (n % 4 hits): one thread.
    if (blockIdx.x == 0 && threadIdx.x == 0) {
        for (long i = nquads * 4; i < n; i++) {
            float4 v = g_shower[sid[i] + 1];
            out[i]       = v.x;
            out[i + n]   = v.y;
            out[i + 2*n] = v.z;
            out[i + 3*n] = v.w;
        }
    }
}

extern "C" void kernel_launch(void* const* d_in, const int* in_sizes, int n_in,
                              void* d_out, int out_size) {
    const int*   pred_sid = (const int*)  d_in[0];
    const float* pcf      = (const float*)d_in[1];
    const float* energy   = (const float*)d_in[2];
    const int*   rid      = (const int*)  d_in[3];
    // d_in[4] = pred_beta (unused)
    const int*   a_tracks = (const int*)  d_in[5];
    const int*   a_hits   = (const int*)  d_in[6];
    float*       out      = (float*)d_out;

    long n_hits   = in_sizes[0];
    int n_showers = in_sizes[5];
    int nseg      = n_showers + 1;
    if (nseg > MAX_SEG) nseg = MAX_SEG;

    static int sm_count = 0;
    if (sm_count == 0) {
        cudaDeviceProp prop;
        cudaGetDeviceProperties(&prop, 0);
        sm_count = prop.multiProcessorCount;
        if (sm_count <= 0) sm_count = 148;
    }

    const int TPB = 256;
    long wave = 8L * sm_count;   // CTAs in exactly one resident wave

    long ngroups = n_hits / 8;
    long sc_grid = (ngroups + TPB - 1) / TPB;
    if (sc_grid > wave) sc_grid = wave;
    if (sc_grid < 1) sc_grid = 1;
    scatter8_gs_kernel<<<(unsigned)sc_grid, TPB>>>(pred_sid, energy, rid,
                                                   ngroups, n_hits);

    corr_kernel<<<(nseg + TPB - 1) / TPB, TPB>>>(pred_sid, pcf, a_tracks, a_hits,
                                                 (int)n_hits, nseg);

    long nquads = n_hits / 4;
    long ga_grid = (nquads + TPB - 1) / TPB;
    if (ga_grid > wave) ga_grid = wave;
    if (ga_grid < 1) ga_grid = 1;
    gather_gs_kernel<<<(unsigned)ga_grid, TPB>>>(pred_sid, out, nquads, n_hits);
}

// round 10
// speedup vs baseline: 1.0509x; 1.0509x over previous
#include <cuda_runtime.h>
#include <cuda_bf16.h>

#define MAX_SEG 16384
#define PAD 32   // one float counter per 128B L2 LINE (bits>=8 feed LTS hash)

// Padded scatter accumulators: track/hit in separate arrays, one counter per
// 128B line (no two hot atomics share an L2 line OR sector). Zero-initialized
// at module load; corr_kernel self-cleans after reading, so every launch
// starts from a clean state.
__device__ float g_track[MAX_SEG * PAD];
__device__ float g_hit[MAX_SEG * PAD];

// Packed table for the gather phase: ONE 16B read per hit.
//   x = e_track_raw  y = e_track_corr  z = e_hit_raw  w = e_hit_corr
__device__ float4 g_shower[MAX_SEG];

__device__ __forceinline__ void stcs_f4(float4* p, float4 v) {
    asm volatile("st.global.cs.v4.f32 [%0], {%1,%2,%3,%4};"
                 :: "l"(p), "f"(v.x), "f"(v.y), "f"(v.z), "f"(v.w)
                 : "memory");
}

// ---------------------------------------------------------------------------
// Kernel 1: scatter — grid-stride over groups of 8 hits, int32 indexing and
// __launch_bounds__(256,8) to keep regs <= 32 (8 CTAs/SM). Loads
// front-batched, then 8 predicated REDs. Noise hits (sid == -1) contribute
// exactly 0 in the reference -> skipped. recHitID==1 -> track, ==0 -> hit.
// ---------------------------------------------------------------------------
__global__ void __launch_bounds__(256, 8) scatter8_gs_kernel(
        const int* __restrict__ sid,
        const float* __restrict__ energy,
        const int* __restrict__ rid,
        int ngroups,           // n/8 groups of 8 hits
        int n) {
    int stride = gridDim.x * blockDim.x;
    for (int t = blockIdx.x * blockDim.x + threadIdx.x; t < ngroups;
         t += stride) {
        int4   s0 = __ldg((const int4*)(sid)      + 2*t);
        int4   s1 = __ldg((const int4*)(sid)      + 2*t + 1);
        float4 e0 = __ldg((const float4*)(energy) + 2*t);
        float4 e1 = __ldg((const float4*)(energy) + 2*t + 1);
        int4   r0 = __ldg((const int4*)(rid)      + 2*t);
        int4   r1 = __ldg((const int4*)(rid)      + 2*t + 1);
        int   s[8] = {s0.x, s0.y, s0.z, s0.w, s1.x, s1.y, s1.z, s1.w};
        float e[8] = {e0.x, e0.y, e0.z, e0.w, e1.x, e1.y, e1.z, e1.w};
        int   r[8] = {r0.x, r0.y, r0.z, r0.w, r1.x, r1.y, r1.z, r1.w};
#pragma unroll
        for (int k = 0; k < 8; k++) {
            if (s[k] >= 0) {
                float* p = (r[k] == 1) ? &g_track[(s[k] + 1) * PAD]
                                       : &g_hit[(s[k] + 1) * PAD];
                atomicAdd(p, e[k]);
            }
        }
    }
    // Tail (n % 8 hits): one thread, <= 7 ops.
    if (blockIdx.x == 0 && threadIdx.x == 0) {
        for (int i = ngroups * 8; i < n; i++) {
            int sv = sid[i];
            if (sv >= 0) {
                float* p = (rid[i] == 1) ? &g_track[(sv + 1) * PAD]
                                         : &g_hit[(sv + 1) * PAD];
                atomicAdd(p, energy[i]);
            }
        }
    }
}

// ---------------------------------------------------------------------------
// Kernel 2: per-shower correction + repack into the float4 table + self-clean.
// corr[s] (s>=1) = pcf_ext[alpha_idx[s-1]], pcf_ext[j] = pcf[j] if j < n_hits
// and sid[j] != -1, else 0. corr[0] = 0.
// ---------------------------------------------------------------------------
__global__ void corr_kernel(const int* __restrict__ sid,
                            const float* __restrict__ pcf,
                            const int* __restrict__ a_tracks,
                            const int* __restrict__ a_hits,
                            int n_hits, int nseg) {
    int s = blockIdx.x * blockDim.x + threadIdx.x;
    if (s >= nseg) return;
    float ct = 0.f, ch = 0.f;
    if (s > 0) {
        int jt = a_tracks[s - 1];
        if (jt >= 0 && jt < n_hits && __ldg(sid + jt) != -1) ct = __ldg(pcf + jt);
        int jh = a_hits[s - 1];
        if (jh >= 0 && jh < n_hits && __ldg(sid + jh) != -1) ch = __ldg(pcf + jh);
    }
    float et = g_track[s * PAD];
    float eh = g_hit[s * PAD];
    g_shower[s] = make_float4(et, et * ct, eh, eh * ch);
    g_track[s * PAD] = 0.f;   // clean for the next launch
    g_hit[s * PAD]   = 0.f;
}

// ---------------------------------------------------------------------------
// Kernel 3: gather — grid-stride, 4 hits/iter: 1 int4 sid load ->
// 4 independent random 16B table reads -> 4 coalesced float4 STREAMING stores.
//   [0,n) e_track_raw [n,2n) e_track_corr [2n,3n) e_hit_raw [3n,4n) e_hit_corr
// ---------------------------------------------------------------------------
__global__ void __launch_bounds__(256, 8) gather_gs_kernel(
        const int* __restrict__ sid,
        float* __restrict__ out,
        int nquads, int n) {
    int stride = gridDim.x * blockDim.x;
    for (int t = blockIdx.x * blockDim.x + threadIdx.x; t < nquads;
         t += stride) {
        int4 s4 = __ldg((const int4*)(sid) + t);
        float4 v0 = g_shower[s4.x + 1];
        float4 v1 = g_shower[s4.y + 1];
        float4 v2 = g_shower[s4.z + 1];
        float4 v3 = g_shower[s4.w + 1];
        stcs_f4((float4*)(out)          + t, make_float4(v0.x, v1.x, v2.x, v3.x));
        stcs_f4((float4*)(out + n)      + t, make_float4(v0.y, v1.y, v2.y, v3.y));
        stcs_f4((float4*)(out + 2ll*n)  + t, make_float4(v0.z, v1.z, v2.z, v3.z));
        stcs_f4((float4*)(out + 3ll*n)  + t, make_float4(v0.w, v1.w, v2.w, v3.w));
    }
    // Tail (n % 4 hits): one thread.
    if (blockIdx.x == 0 && threadIdx.x == 0) {
        for (int i = nquads * 4; i < n; i++) {
            float4 v = g_shower[sid[i] + 1];
            out[i]          = v.x;
            out[i + 1ll*n]  = v.y;
            out[i + 2ll*n]  = v.z;
            out[i + 3ll*n]  = v.w;
        }
    }
}

extern "C" void kernel_launch(void* const* d_in, const int* in_sizes, int n_in,
                              void* d_out, int out_size) {
    const int*   pred_sid = (const int*)  d_in[0];
    const float* pcf      = (const float*)d_in[1];
    const float* energy   = (const float*)d_in[2];
    const int*   rid      = (const int*)  d_in[3];
    // d_in[4] = pred_beta (unused)
    const int*   a_tracks = (const int*)  d_in[5];
    const int*   a_hits   = (const int*)  d_in[6];
    float*       out      = (float*)d_out;

    int n_hits    = in_sizes[0];
    int n_showers = in_sizes[5];
    int nseg      = n_showers + 1;
    if (nseg > MAX_SEG) nseg = MAX_SEG;

    static int sm_count = 0;
    if (sm_count == 0) {
        cudaDeviceProp prop;
        cudaGetDeviceProperties(&prop, 0);
        sm_count = prop.multiProcessorCount;
        if (sm_count <= 0) sm_count = 148;
    }

    const int TPB = 256;
    long wave = 8L * sm_count;   // exactly one resident wave @ 8 CTAs/SM

    int ngroups = n_hits / 8;
    long sc_grid = ((long)ngroups + TPB - 1) / TPB;
    if (sc_grid > wave) sc_grid = wave;
    if (sc_grid < 1) sc_grid = 1;
    scatter8_gs_kernel<<<(unsigned)sc_grid, TPB>>>(pred_sid, energy, rid,
                                                   ngroups, n_hits);

    corr_kernel<<<(nseg + TPB - 1) / TPB, TPB>>>(pred_sid, pcf, a_tracks, a_hits,
                                                 n_hits, nseg);

    int nquads = n_hits / 4;
    long ga_grid = ((long)nquads + TPB - 1) / TPB;
    if (ga_grid > wave) ga_grid = wave;
    if (ga_grid < 1) ga_grid = 1;
    gather_gs_kernel<<<(unsigned)ga_grid, TPB>>>(pred_sid, out, nquads, n_hits);
}